// round 14
// baseline (speedup 1.0000x reference)
#include <cuda_runtime.h>
#include <cuda_fp16.h>
#include <cstdint>

#define DEV_INLINE __device__ __forceinline__

using f16 = __half;

constexpr int B_SZ  = 4;
constexpr int T_LEN = 4096;
constexpr int DM    = 1024;
constexpr int NS    = 256;
constexpr int DFF   = 2736;
constexpr int DFFP  = 2752;            // padded to /64
constexpr int MROWS = B_SZ * T_LEN;    // 16384
constexpr float EPSN = 1e-6f;

constexpr int CLEN   = 64;
constexpr int NCHUNK = T_LEN / CLEN;   // 64
constexpr int SCAN_GRID = B_SZ * NCHUNK;  // 256

// ------------------------------- scratch -----------------------------------
__device__ float g_Bu[(size_t)MROWS * NS];
__device__ float g_x1[(size_t)MROWS * DM];
__device__ float g_Hc[SCAN_GRID * NS];
__device__ int   g_scan_ctr;            // monotone ticket counter (never reset)

__device__ f16 g_uh [(size_t)MROWS * DM];
__device__ f16 g_hsh[(size_t)MROWS * NS];
__device__ f16 g_zh [(size_t)MROWS * DM];
__device__ f16 g_gh [(size_t)MROWS * DFFP];

// fp16 weights (single copy; padded tails zero)
__device__ f16 g_Bw16[NS * DM];
__device__ f16 g_Cw16[DM * NS];
__device__ f16 g_w116[DFFP * DM];
__device__ f16 g_w316[DFFP * DM];
__device__ f16 g_w216[DM * DFFP];

// ------------------------------- PTX helpers -------------------------------
DEV_INLINE uint32_t s2u(const void* p) {
    return (uint32_t)__cvta_generic_to_shared(p);
}
DEV_INLINE void cpa16(uint32_t dst, const void* src) {
    asm volatile("cp.async.cg.shared.global [%0], [%1], 16;\n"
                 :: "r"(dst), "l"(src));
}
DEV_INLINE void cp_commit() { asm volatile("cp.async.commit_group;\n"); }
template <int N> DEV_INLINE void cp_wait() {
    asm volatile("cp.async.wait_group %0;\n" :: "n"(N));
}
DEV_INLINE void ldm4(uint32_t* r, uint32_t a) {
    asm volatile("ldmatrix.sync.aligned.m8n8.x4.shared.b16 {%0,%1,%2,%3}, [%4];\n"
                 : "=r"(r[0]), "=r"(r[1]), "=r"(r[2]), "=r"(r[3]) : "r"(a));
}
DEV_INLINE void mma16816(float* c, const uint32_t* a, const uint32_t* b) {
    asm volatile(
        "mma.sync.aligned.m16n8k16.row.col.f32.f16.f16.f32 "
        "{%0,%1,%2,%3}, {%4,%5,%6,%7}, {%8,%9}, {%0,%1,%2,%3};\n"
        : "+f"(c[0]), "+f"(c[1]), "+f"(c[2]), "+f"(c[3])
        : "r"(a[0]), "r"(a[1]), "r"(a[2]), "r"(a[3]), "r"(b[0]), "r"(b[1]));
}

// -------------------- fused rmsnorm1 + weight conversion --------------------
constexpr int CV0 = NS * DM;                 // Bw
constexpr int CV1 = CV0 + DM * NS;           // Cw
constexpr int CV2 = CV1 + DFFP * DM;         // w1 (padrow)
constexpr int CV3 = CV2 + DFFP * DM;         // w3 (padrow)
constexpr int CV4 = CV3 + DM * DFFP;         // w2 (padcol)
constexpr int CONVB = (CV4 / 2 + 255) / 256;

DEV_INLINE void rmsnorm_row(const float* __restrict__ x,
                            const float* __restrict__ w,
                            f16* __restrict__ oh, int row, int tid)
{
    float4 v = reinterpret_cast<const float4*>(x + (size_t)row * DM)[tid];
    float ss = v.x*v.x + v.y*v.y + v.z*v.z + v.w*v.w;
    #pragma unroll
    for (int o = 16; o; o >>= 1) ss += __shfl_xor_sync(0xffffffffu, ss, o);
    __shared__ float red[8];
    if ((tid & 31) == 0) red[tid >> 5] = ss;
    __syncthreads();
    float tot = red[0]+red[1]+red[2]+red[3]+red[4]+red[5]+red[6]+red[7];
    float inv = rsqrtf(tot * (1.0f / (float)DM) + EPSN);
    float4 wv = reinterpret_cast<const float4*>(w)[tid];
    __half2* ph = reinterpret_cast<__half2*>(oh + (size_t)row * DM);
    ph[tid*2]   = __half2(__float2half_rn(v.x*inv*wv.x), __float2half_rn(v.y*inv*wv.y));
    ph[tid*2+1] = __half2(__float2half_rn(v.z*inv*wv.z), __float2half_rn(v.w*inv*wv.w));
}

__global__ void __launch_bounds__(256)
rms1_conv_kernel(const float* __restrict__ x, const float* __restrict__ ssw,
                 f16* __restrict__ uh,
                 const float* __restrict__ B_w, const float* __restrict__ C_w,
                 const float* __restrict__ w1,  const float* __restrict__ w3,
                 const float* __restrict__ w2,
                 f16* __restrict__ Bw16, f16* __restrict__ Cw16,
                 f16* __restrict__ w116, f16* __restrict__ w316,
                 f16* __restrict__ w216)
{
    if (blockIdx.x < MROWS) {
        rmsnorm_row(x, ssw, uh, blockIdx.x, threadIdx.x);
        return;
    }
    const int i = 2 * ((blockIdx.x - MROWS) * blockDim.x + threadIdx.x);
    if (i >= CV4) return;
    float v0, v1;
    f16* dst;
    if (i < CV0) {
        v0 = B_w[i]; v1 = B_w[i + 1]; dst = Bw16 + i;
    } else if (i < CV1) {
        int j = i - CV0;
        v0 = C_w[j]; v1 = C_w[j + 1]; dst = Cw16 + j;
    } else if (i < CV2) {
        int j = i - CV1;
        int r = j >> 10, c = j & 1023;              // DM = 1024
        bool ok = r < DFF;
        v0 = ok ? w1[(size_t)r * DM + c]     : 0.0f;
        v1 = ok ? w1[(size_t)r * DM + c + 1] : 0.0f;
        dst = w116 + j;
    } else if (i < CV3) {
        int j = i - CV2;
        int r = j >> 10, c = j & 1023;
        bool ok = r < DFF;
        v0 = ok ? w3[(size_t)r * DM + c]     : 0.0f;
        v1 = ok ? w3[(size_t)r * DM + c + 1] : 0.0f;
        dst = w316 + j;
    } else {
        int j = i - CV3;
        int r = j / DFFP, c = j - r * DFFP;         // c even; row never straddled
        v0 = (c     < DFF) ? w2[(size_t)r * DFF + c]     : 0.0f;
        v1 = (c + 1 < DFF) ? w2[(size_t)r * DFF + c + 1] : 0.0f;
        dst = w216 + j;
    }
    *reinterpret_cast<__half2*>(dst) =
        __half2(__float2half_rn(v0), __float2half_rn(v1));
}

// ------------------------------- rmsnorm (step 5) ---------------------------
__global__ void __launch_bounds__(256)
rmsnorm_f16_kernel(const float* __restrict__ x, const float* __restrict__ w,
                   f16* __restrict__ oh)
{
    rmsnorm_row(x, w, oh, blockIdx.x, threadIdx.x);
}

// --------------------- fused scan (local + barrier + fixup) -----------------
DEV_INLINE float lam_of(const float* ll, int n) {
    return 1.0f / (1.0f + expf(-ll[n]));
}

__global__ void __launch_bounds__(NS)
scan_fused_kernel(const float* __restrict__ Bu, float* __restrict__ Hc,
                  const float* __restrict__ ll, f16* __restrict__ oh)
{
    extern __shared__ float sh[];                 // [CLEN][NS]
    const int bc = blockIdx.x, b = bc / NCHUNK, c = bc % NCHUNK;
    const int n = threadIdx.x;
    const float lam = lam_of(ll, n);
    const size_t base = ((size_t)b * T_LEN + (size_t)c * CLEN) * NS + n;

    // phase 1: local scan into smem, chunk carry to global
    float h = 0.0f;
    #pragma unroll 4
    for (int i = 0; i < CLEN; ++i) {
        h = fmaf(lam, h, Bu[base + (size_t)i * NS]);
        sh[i * NS + n] = h;
    }
    Hc[bc * NS + n] = h;

    // software grid barrier (ticket-based; monotone counter, replay-safe)
    __shared__ int s_target;
    __syncthreads();                // all Hc stores issued program-order above
    if (n == 0) {
        __threadfence();            // release our Hc writes GPU-wide
        int ticket = atomicAdd(&g_scan_ctr, 1);
        s_target = (ticket / SCAN_GRID + 1) * SCAN_GRID;
    }
    __syncthreads();
    {
        const int target = s_target;
        volatile int* vc = &g_scan_ctr;
        while (*vc < target) { }
        __threadfence();            // acquire: other CTAs' Hc now visible
    }

    // phase 2: carry prefix (identical fmaf chain) + fixup
    float lamP = lam;
    #pragma unroll
    for (int j = 0; j < 6; ++j) lamP *= lamP;     // lam^64 == lam^CLEN
    float h0 = 0.0f;
    for (int j = 0; j < c; ++j)
        h0 = fmaf(lamP, h0, Hc[(b * NCHUNK + j) * NS + n]);
    float p = lam;
    #pragma unroll 4
    for (int i = 0; i < CLEN; ++i) {
        float v = fmaf(p, h0, sh[i * NS + n]);    // h0==0 for c==0
        oh[base + (size_t)i * NS] = __float2half_rn(v);
        p *= lam;
    }
}
constexpr int SMEM_SCAN = CLEN * NS * 4;          // 65536

// ----------------- fp16 GEMM, BK=32, 3-stage (SSM sizes) -------------------
constexpr int RSB   = 80;               // 32 f16 + 16B pad
constexpr int TILE1 = 128 * RSB;        // 10240
constexpr int STG   = 2 * TILE1;        // 20480
constexpr int SMEM_GEMM = 3 * STG;      // 61440

enum { EPI_NONE = 0, EPI_SSM = 1 };

template <int EPI>
__global__ void __launch_bounds__(256)
gemm_kernel(const f16* __restrict__ Ah, const f16* __restrict__ Bw,
            float* __restrict__ C, int M, int N, int K,
            const float* __restrict__ res, const f16* __restrict__ uaux,
            const float* __restrict__ dskip)
{
    extern __shared__ char smem[];
    const uint32_t sb = s2u(smem);
    const int tid = threadIdx.x, lane = tid & 31, wid = tid >> 5;
    const int mBase = blockIdx.y * 128, nBase = blockIdx.x * 128;
    const int wm = wid >> 2, wn = wid & 3;

    const int lr = tid >> 1;
    const int lc = (tid & 1) * 2;
    const size_t aoff = (size_t)(mBase + lr) * K;
    const size_t boff = (size_t)(nBase + lr) * K;

    const int lrow = (lane & 7) | (((lane >> 3) & 1) << 3);
    const int lkb  = lane >> 4;

    float acc[4][4][4];
    #pragma unroll
    for (int i = 0; i < 4; ++i)
        #pragma unroll
        for (int j = 0; j < 4; ++j)
            #pragma unroll
            for (int q = 0; q < 4; ++q) acc[i][j][q] = 0.0f;

    const int KT = K / 32;

    auto LOAD = [&](int kt, int s) {
        uint32_t base = sb + s * STG;
        #pragma unroll
        for (int j = 0; j < 2; ++j) {
            int c = lc + j;
            uint32_t dst = base + lr * RSB + c * 16;
            cpa16(dst,         Ah + aoff + kt * 32 + c * 8);
            cpa16(dst + TILE1, Bw + boff + kt * 32 + c * 8);
        }
        cp_commit();
    };

    LOAD(0, 0);
    if (KT > 1) LOAD(1, 1);

    int s = 0;
    for (int kt = 0; kt < KT; ++kt) {
        cp_wait<1>();
        __syncthreads();
        if (kt + 2 < KT) LOAD(kt + 2, (s + 2 >= 3) ? s - 1 : s + 2);

        const uint32_t base = sb + s * STG;
        #pragma unroll
        for (int ss = 0; ss < 2; ++ss) {
            const uint32_t kofs = ss * 32;
            uint32_t af[4][4], bf[4][2];
            #pragma unroll
            for (int mt = 0; mt < 4; ++mt) {
                uint32_t ad = base + (uint32_t)(wm*64 + mt*16 + lrow) * RSB
                            + kofs + lkb * 16;
                ldm4(af[mt], ad);
            }
            #pragma unroll
            for (int p = 0; p < 2; ++p) {
                uint32_t bd = base + TILE1
                            + (uint32_t)(wn*32 + p*16 + lrow) * RSB
                            + kofs + lkb * 16;
                uint32_t r[4];
                ldm4(r, bd);
                bf[2*p][0]   = r[0]; bf[2*p][1]   = r[2];
                bf[2*p+1][0] = r[1]; bf[2*p+1][1] = r[3];
            }
            #pragma unroll
            for (int mt = 0; mt < 4; ++mt)
                #pragma unroll
                for (int nt = 0; nt < 4; ++nt)
                    mma16816(acc[mt][nt], af[mt], bf[nt]);
        }
        s = (s + 1 >= 3) ? 0 : s + 1;
    }
    __syncthreads();

    const int g = lane >> 2, t = lane & 3;
    #pragma unroll
    for (int mt = 0; mt < 4; ++mt) {
        #pragma unroll
        for (int nt = 0; nt < 4; ++nt) {
            const int col  = nBase + wn*32 + nt*8 + t*2;
            const int row0 = mBase + wm*64 + mt*16 + g;
            const int row1 = row0 + 8;
            float2 v0 = make_float2(acc[mt][nt][0], acc[mt][nt][1]);
            float2 v1 = make_float2(acc[mt][nt][2], acc[mt][nt][3]);
            const size_t o0 = (size_t)row0 * N + col;
            const size_t o1 = (size_t)row1 * N + col;
            if (EPI == EPI_SSM) {
                float2 d  = *reinterpret_cast<const float2*>(dskip + col);
                float2 r0 = *reinterpret_cast<const float2*>(res + o0);
                float2 r1 = *reinterpret_cast<const float2*>(res + o1);
                v0.x += r0.x; v0.y += r0.y;
                v1.x += r1.x; v1.y += r1.y;
                if (d.x != 0.0f || d.y != 0.0f) {   // skip u stream when D_skip==0
                    float2 u0 = __half22float2(
                        *reinterpret_cast<const __half2*>(uaux + o0));
                    float2 u1 = __half22float2(
                        *reinterpret_cast<const __half2*>(uaux + o1));
                    v0.x += d.x * u0.x; v0.y += d.y * u0.y;
                    v1.x += d.x * u1.x; v1.y += d.y * u1.y;
                }
            }
            *reinterpret_cast<float2*>(C + o0) = v0;
            *reinterpret_cast<float2*>(C + o1) = v1;
        }
    }
}

// ----------------- fp16 GEMM, BK=64, 2-stage (down GEMM) --------------------
// Wider per-iteration scheduling window: 4 k16 sub-steps between barriers.
constexpr int RSB64   = 144;             // 64 f16 (128B) + 16B pad
constexpr int TILEA64 = 128 * RSB64;     // 18432
constexpr int STG64   = 2 * TILEA64;     // 36864
constexpr int SMEM_G64 = 2 * STG64;      // 73728

__global__ void __launch_bounds__(256)
gemm64_kernel(const f16* __restrict__ Ah, const f16* __restrict__ Bw,
              float* __restrict__ C, int M, int N, int K,
              const float* __restrict__ res)
{
    extern __shared__ char smem[];
    const uint32_t sb = s2u(smem);
    const int tid = threadIdx.x, lane = tid & 31, wid = tid >> 5;
    const int mBase = blockIdx.y * 128, nBase = blockIdx.x * 128;
    const int wm = wid >> 2, wn = wid & 3;

    const int lr = tid >> 1;
    const int lc = (tid & 1) * 4;           // 4 chunks of 16B per thread
    const size_t aoff = (size_t)(mBase + lr) * K;
    const size_t boff = (size_t)(nBase + lr) * K;

    const int lrow = (lane & 7) | (((lane >> 3) & 1) << 3);
    const int lkb  = lane >> 4;

    float acc[4][4][4];
    #pragma unroll
    for (int i = 0; i < 4; ++i)
        #pragma unroll
        for (int j = 0; j < 4; ++j)
            #pragma unroll
            for (int q = 0; q < 4; ++q) acc[i][j][q] = 0.0f;

    const int KT = K / 64;

    auto LOAD = [&](int kt, int s) {
        uint32_t base = sb + s * STG64;
        #pragma unroll
        for (int j = 0; j < 4; ++j) {
            int c = lc + j;
            uint32_t dst = base + lr * RSB64 + c * 16;
            cpa16(dst,           Ah + aoff + kt * 64 + c * 8);
            cpa16(dst + TILEA64, Bw + boff + kt * 64 + c * 8);
        }
        cp_commit();
    };

    LOAD(0, 0);

    for (int kt = 0; kt < KT; ++kt) {
        cp_wait<0>();
        __syncthreads();
        if (kt + 1 < KT) LOAD(kt + 1, (kt + 1) & 1);

        const uint32_t base = sb + (kt & 1) * STG64;
        #pragma unroll
        for (int ss = 0; ss < 4; ++ss) {
            const uint32_t kofs = ss * 32;
            uint32_t af[4][4], bf[4][2];
            #pragma unroll
            for (int mt = 0; mt < 4; ++mt) {
                uint32_t ad = base + (uint32_t)(wm*64 + mt*16 + lrow) * RSB64
                            + kofs + lkb * 16;
                ldm4(af[mt], ad);
            }
            #pragma unroll
            for (int p = 0; p < 2; ++p) {
                uint32_t bd = base + TILEA64
                            + (uint32_t)(wn*32 + p*16 + lrow) * RSB64
                            + kofs + lkb * 16;
                uint32_t r[4];
                ldm4(r, bd);
                bf[2*p][0]   = r[0]; bf[2*p][1]   = r[2];
                bf[2*p+1][0] = r[1]; bf[2*p+1][1] = r[3];
            }
            #pragma unroll
            for (int mt = 0; mt < 4; ++mt)
                #pragma unroll
                for (int nt = 0; nt < 4; ++nt)
                    mma16816(acc[mt][nt], af[mt], bf[nt]);
        }
        __syncthreads();
    }

    const int g = lane >> 2, t = lane & 3;
    #pragma unroll
    for (int mt = 0; mt < 4; ++mt) {
        #pragma unroll
        for (int nt = 0; nt < 4; ++nt) {
            const int col  = nBase + wn*32 + nt*8 + t*2;
            const int row0 = mBase + wm*64 + mt*16 + g;
            const int row1 = row0 + 8;
            float2 v0 = make_float2(acc[mt][nt][0], acc[mt][nt][1]);
            float2 v1 = make_float2(acc[mt][nt][2], acc[mt][nt][3]);
            const size_t o0 = (size_t)row0 * N + col;
            const size_t o1 = (size_t)row1 * N + col;
            float2 r0 = *reinterpret_cast<const float2*>(res + o0);
            float2 r1 = *reinterpret_cast<const float2*>(res + o1);
            v0.x += r0.x; v0.y += r0.y;
            v1.x += r1.x; v1.y += r1.y;
            *reinterpret_cast<float2*>(C + o0) = v0;
            *reinterpret_cast<float2*>(C + o1) = v1;
        }
    }
}

// ------------- dual SwiGLU fp16 GEMM, BK=64, 2-stage (BN=64) ----------------
constexpr int TILB64 = 64 * RSB64;              // 9216
constexpr int STG_D64 = TILEA64 + 2 * TILB64;   // 36864
constexpr int SMEM_D64 = 2 * STG_D64;           // 73728

__global__ void __launch_bounds__(256)
swiglu_kernel(const f16* __restrict__ Ah,
              const f16* __restrict__ W1, const f16* __restrict__ W3,
              f16* __restrict__ Gh, int M, int Kp, int K)
{
    extern __shared__ char smem[];
    const uint32_t sb = s2u(smem);
    const int tid = threadIdx.x, lane = tid & 31, wid = tid >> 5;
    const int mBase = blockIdx.y * 128, nBase = blockIdx.x * 64;
    const int wm = wid >> 2, wn = wid & 3;

    const int lra = tid >> 1, lca = (tid & 1) * 4;   // A: 2 thr/row, 4 chunks
    // B: 64 rows x 8 chunks x 2 mats = 1024 cpa16 / 256 thr = 4 each
    const int bmat = tid >> 7;                       // 0: W1, 1: W3
    const int lrb  = (tid & 127) >> 1;               // row 0..63
    const int lcb  = (tid & 1) * 4;                  // 4 chunks
    const size_t aoff = (size_t)(mBase + lra) * K;
    const f16* bsrc = (bmat == 0 ? W1 : W3);
    const size_t boff = (size_t)(nBase + lrb) * K;   // weights padded

    const int lrow = (lane & 7) | (((lane >> 3) & 1) << 3);
    const int lkb  = lane >> 4;

    float accG[4][2][4], accV[4][2][4];
    #pragma unroll
    for (int i = 0; i < 4; ++i)
        #pragma unroll
        for (int j = 0; j < 2; ++j)
            #pragma unroll
            for (int q = 0; q < 4; ++q) { accG[i][j][q] = 0.0f; accV[i][j][q] = 0.0f; }

    const int KT = K / 64;

    auto LOAD = [&](int kt, int s) {
        uint32_t base = sb + s * STG_D64;
        #pragma unroll
        for (int j = 0; j < 4; ++j) {
            int c = lca + j;
            cpa16(base + lra * RSB64 + c * 16, Ah + aoff + kt * 64 + c * 8);
        }
        #pragma unroll
        for (int j = 0; j < 4; ++j) {
            int c = lcb + j;
            cpa16(base + TILEA64 + bmat * TILB64 + lrb * RSB64 + c * 16,
                  bsrc + boff + kt * 64 + c * 8);
        }
        cp_commit();
    };

    LOAD(0, 0);

    for (int kt = 0; kt < KT; ++kt) {
        cp_wait<0>();
        __syncthreads();
        if (kt + 1 < KT) LOAD(kt + 1, (kt + 1) & 1);

        const uint32_t base = sb + (kt & 1) * STG_D64;
        #pragma unroll
        for (int ss = 0; ss < 4; ++ss) {
            const uint32_t kofs = ss * 32;
            uint32_t af[4][4];
            uint32_t b1[2][2], b3[2][2];
            #pragma unroll
            for (int mt = 0; mt < 4; ++mt) {
                uint32_t ad = base + (uint32_t)(wm*64 + mt*16 + lrow) * RSB64
                            + kofs + lkb * 16;
                ldm4(af[mt], ad);
            }
            {
                uint32_t bd = base + TILEA64
                            + (uint32_t)(wn*16 + lrow) * RSB64 + kofs + lkb * 16;
                uint32_t r[4];
                ldm4(r, bd);
                b1[0][0]=r[0]; b1[0][1]=r[2]; b1[1][0]=r[1]; b1[1][1]=r[3];
                ldm4(r, bd + TILB64);
                b3[0][0]=r[0]; b3[0][1]=r[2]; b3[1][0]=r[1]; b3[1][1]=r[3];
            }
            #pragma unroll
            for (int mt = 0; mt < 4; ++mt)
                #pragma unroll
                for (int nt = 0; nt < 2; ++nt) {
                    mma16816(accG[mt][nt], af[mt], b1[nt]);
                    mma16816(accV[mt][nt], af[mt], b3[nt]);
                }
        }
        __syncthreads();
    }

    // epilogue: o = silu(gate) * val, fp16 round, strided Kp
    const int g = lane >> 2, t = lane & 3;
    #pragma unroll
    for (int mt = 0; mt < 4; ++mt) {
        #pragma unroll
        for (int nt = 0; nt < 2; ++nt) {
            const int col  = nBase + wn*16 + nt*8 + t*2;
            const int row0 = mBase + wm*64 + mt*16 + g;
            #pragma unroll
            for (int half = 0; half < 2; ++half) {
                const int row = row0 + half * 8;
                float gg0 = accG[mt][nt][half*2],   gg1 = accG[mt][nt][half*2+1];
                float vv0 = accV[mt][nt][half*2],   vv1 = accV[mt][nt][half*2+1];
                float o0 = gg0 / (1.0f + __expf(-gg0)) * vv0;
                float o1 = gg1 / (1.0f + __expf(-gg1)) * vv1;
                const size_t off = (size_t)row * Kp + col;
                *reinterpret_cast<__half2*>(Gh + off) =
                    __half2(__float2half_rn(o0), __float2half_rn(o1));
            }
        }
    }
}

// ------------------------------- launch -------------------------------------
extern "C" void kernel_launch(void* const* d_in, const int* in_sizes, int n_in,
                              void* d_out, int out_size)
{
    (void)in_sizes; (void)n_in; (void)out_size;
    const float* x        = (const float*)d_in[0];
    const float* log_lam  = (const float*)d_in[1];
    const float* B_w      = (const float*)d_in[2];
    const float* C_w      = (const float*)d_in[3];
    const float* D_skip   = (const float*)d_in[4];
    const float* ssm_w    = (const float*)d_in[5];
    const float* ffn_w    = (const float*)d_in[6];
    const float* w1       = (const float*)d_in[7];
    const float* w2       = (const float*)d_in[8];
    const float* w3       = (const float*)d_in[9];
    float* out = (float*)d_out;

    cudaFuncSetAttribute((const void*)gemm_kernel<EPI_NONE>,
        cudaFuncAttributeMaxDynamicSharedMemorySize, SMEM_GEMM);
    cudaFuncSetAttribute((const void*)gemm_kernel<EPI_SSM>,
        cudaFuncAttributeMaxDynamicSharedMemorySize, SMEM_GEMM);
    cudaFuncSetAttribute((const void*)gemm64_kernel,
        cudaFuncAttributeMaxDynamicSharedMemorySize, SMEM_G64);
    cudaFuncSetAttribute((const void*)swiglu_kernel,
        cudaFuncAttributeMaxDynamicSharedMemorySize, SMEM_D64);
    cudaFuncSetAttribute((const void*)scan_fused_kernel,
        cudaFuncAttributeMaxDynamicSharedMemorySize, SMEM_SCAN);

    float *Bu, *x1, *Hc;
    f16 *uh, *hsh, *zh, *gh;
    f16 *Bw16, *Cw16, *w116, *w316, *w216;
    cudaGetSymbolAddress((void**)&Bu,   g_Bu);
    cudaGetSymbolAddress((void**)&x1,   g_x1);
    cudaGetSymbolAddress((void**)&Hc,   g_Hc);
    cudaGetSymbolAddress((void**)&uh,   g_uh);
    cudaGetSymbolAddress((void**)&hsh,  g_hsh);
    cudaGetSymbolAddress((void**)&zh,   g_zh);
    cudaGetSymbolAddress((void**)&gh,   g_gh);
    cudaGetSymbolAddress((void**)&Bw16, g_Bw16);
    cudaGetSymbolAddress((void**)&Cw16, g_Cw16);
    cudaGetSymbolAddress((void**)&w116, g_w116);
    cudaGetSymbolAddress((void**)&w316, g_w316);
    cudaGetSymbolAddress((void**)&w216, g_w216);

    // 0+1) uh = fp16(rmsnorm(x, ssm_norm_w)) AND all weight conversions
    rms1_conv_kernel<<<MROWS + CONVB, 256>>>(
        x, ssm_w, uh, B_w, C_w, w1, w3, w2,
        Bw16, Cw16, w116, w316, w216);

    // 2) Bu = u @ B_w^T  [16384, 256], K=1024  (BK=32, 3-stage)
    gemm_kernel<EPI_NONE><<<dim3(NS/128, MROWS/128), 256, SMEM_GEMM>>>(
        uh, Bw16, Bu, MROWS, NS, DM, nullptr, nullptr, nullptr);

    // 3) fused chunked diagonal scan -> hsh (fp16), single launch
    scan_fused_kernel<<<SCAN_GRID, NS, SMEM_SCAN>>>(Bu, Hc, log_lam, hsh);

    // 4) x1 = x + hs @ C_w^T + D_skip * u  [16384, 1024], K=256  (BK=32)
    gemm_kernel<EPI_SSM><<<dim3(DM/128, MROWS/128), 256, SMEM_GEMM>>>(
        hsh, Cw16, x1, MROWS, DM, NS, x, uh, D_skip);

    // 5) zh = fp16(rmsnorm(x1, ffn_norm_w))
    rmsnorm_f16_kernel<<<MROWS, 256>>>(x1, ffn_w, zh);

    // 6) gh = fp16(silu(z@w1^T) * (z@w3^T))  [16384, 2752-padded], K=1024 (BK=64)
    swiglu_kernel<<<dim3(DFFP/64, MROWS/128), 256, SMEM_D64>>>(
        zh, w116, w316, gh, MROWS, DFFP, DM);

    // 7) out = x1 + g @ w2^T  [16384, 1024], K=2752 (BK=64, KT=43)
    gemm64_kernel<<<dim3(DM/128, MROWS/128), 256, SMEM_G64>>>(
        gh, w216, out, MROWS, DM, DFFP, x1);
}

// round 15
// speedup vs baseline: 1.1709x; 1.1709x over previous
#include <cuda_runtime.h>
#include <cuda_fp16.h>
#include <cstdint>

#define DEV_INLINE __device__ __forceinline__

using f16 = __half;

constexpr int B_SZ  = 4;
constexpr int T_LEN = 4096;
constexpr int DM    = 1024;
constexpr int NS    = 256;
constexpr int DFF   = 2736;
constexpr int DFFP  = 2752;            // padded to /64
constexpr int MROWS = B_SZ * T_LEN;    // 16384
constexpr float EPSN = 1e-6f;

constexpr int CLEN   = 64;
constexpr int NCHUNK = T_LEN / CLEN;   // 64
constexpr int SCAN_GRID = B_SZ * NCHUNK;  // 256

// ------------------------------- scratch -----------------------------------
__device__ float g_Bu[(size_t)MROWS * NS];
__device__ float g_x1[(size_t)MROWS * DM];
__device__ float g_Hc[SCAN_GRID * NS];
__device__ int   g_scan_ctr;            // monotone ticket counter (never reset)

__device__ f16 g_uh [(size_t)MROWS * DM];
__device__ f16 g_hsh[(size_t)MROWS * NS];
__device__ f16 g_zh [(size_t)MROWS * DM];
__device__ f16 g_gh [(size_t)MROWS * DFFP];

// fp16 weights (single copy; padded tails zero)
__device__ f16 g_Bw16[NS * DM];
__device__ f16 g_Cw16[DM * NS];
__device__ f16 g_w116[DFFP * DM];
__device__ f16 g_w316[DFFP * DM];
__device__ f16 g_w216[DM * DFFP];

// ------------------------------- PTX helpers -------------------------------
DEV_INLINE uint32_t s2u(const void* p) {
    return (uint32_t)__cvta_generic_to_shared(p);
}
DEV_INLINE void cpa16(uint32_t dst, const void* src) {
    asm volatile("cp.async.cg.shared.global [%0], [%1], 16;\n"
                 :: "r"(dst), "l"(src));
}
DEV_INLINE void cp_commit() { asm volatile("cp.async.commit_group;\n"); }
template <int N> DEV_INLINE void cp_wait() {
    asm volatile("cp.async.wait_group %0;\n" :: "n"(N));
}
DEV_INLINE void ldm4(uint32_t* r, uint32_t a) {
    asm volatile("ldmatrix.sync.aligned.m8n8.x4.shared.b16 {%0,%1,%2,%3}, [%4];\n"
                 : "=r"(r[0]), "=r"(r[1]), "=r"(r[2]), "=r"(r[3]) : "r"(a));
}
DEV_INLINE void mma16816(float* c, const uint32_t* a, const uint32_t* b) {
    asm volatile(
        "mma.sync.aligned.m16n8k16.row.col.f32.f16.f16.f32 "
        "{%0,%1,%2,%3}, {%4,%5,%6,%7}, {%8,%9}, {%0,%1,%2,%3};\n"
        : "+f"(c[0]), "+f"(c[1]), "+f"(c[2]), "+f"(c[3])
        : "r"(a[0]), "r"(a[1]), "r"(a[2]), "r"(a[3]), "r"(b[0]), "r"(b[1]));
}

// -------------------- fused rmsnorm1 + weight conversion --------------------
constexpr int CV0 = NS * DM;                 // Bw
constexpr int CV1 = CV0 + DM * NS;           // Cw
constexpr int CV2 = CV1 + DFFP * DM;         // w1 (padrow)
constexpr int CV3 = CV2 + DFFP * DM;         // w3 (padrow)
constexpr int CV4 = CV3 + DM * DFFP;         // w2 (padcol)
constexpr int CONVB = (CV4 / 2 + 255) / 256;

DEV_INLINE void rmsnorm_row(const float* __restrict__ x,
                            const float* __restrict__ w,
                            f16* __restrict__ oh, int row, int tid)
{
    float4 v = reinterpret_cast<const float4*>(x + (size_t)row * DM)[tid];
    float ss = v.x*v.x + v.y*v.y + v.z*v.z + v.w*v.w;
    #pragma unroll
    for (int o = 16; o; o >>= 1) ss += __shfl_xor_sync(0xffffffffu, ss, o);
    __shared__ float red[8];
    if ((tid & 31) == 0) red[tid >> 5] = ss;
    __syncthreads();
    float tot = red[0]+red[1]+red[2]+red[3]+red[4]+red[5]+red[6]+red[7];
    float inv = rsqrtf(tot * (1.0f / (float)DM) + EPSN);
    float4 wv = reinterpret_cast<const float4*>(w)[tid];
    __half2* ph = reinterpret_cast<__half2*>(oh + (size_t)row * DM);
    ph[tid*2]   = __half2(__float2half_rn(v.x*inv*wv.x), __float2half_rn(v.y*inv*wv.y));
    ph[tid*2+1] = __half2(__float2half_rn(v.z*inv*wv.z), __float2half_rn(v.w*inv*wv.w));
}

__global__ void __launch_bounds__(256)
rms1_conv_kernel(const float* __restrict__ x, const float* __restrict__ ssw,
                 f16* __restrict__ uh,
                 const float* __restrict__ B_w, const float* __restrict__ C_w,
                 const float* __restrict__ w1,  const float* __restrict__ w3,
                 const float* __restrict__ w2,
                 f16* __restrict__ Bw16, f16* __restrict__ Cw16,
                 f16* __restrict__ w116, f16* __restrict__ w316,
                 f16* __restrict__ w216)
{
    if (blockIdx.x < MROWS) {
        rmsnorm_row(x, ssw, uh, blockIdx.x, threadIdx.x);
        return;
    }
    const int i = 2 * ((blockIdx.x - MROWS) * blockDim.x + threadIdx.x);
    if (i >= CV4) return;
    float v0, v1;
    f16* dst;
    if (i < CV0) {
        v0 = B_w[i]; v1 = B_w[i + 1]; dst = Bw16 + i;
    } else if (i < CV1) {
        int j = i - CV0;
        v0 = C_w[j]; v1 = C_w[j + 1]; dst = Cw16 + j;
    } else if (i < CV2) {
        int j = i - CV1;
        int r = j >> 10, c = j & 1023;              // DM = 1024
        bool ok = r < DFF;
        v0 = ok ? w1[(size_t)r * DM + c]     : 0.0f;
        v1 = ok ? w1[(size_t)r * DM + c + 1] : 0.0f;
        dst = w116 + j;
    } else if (i < CV3) {
        int j = i - CV2;
        int r = j >> 10, c = j & 1023;
        bool ok = r < DFF;
        v0 = ok ? w3[(size_t)r * DM + c]     : 0.0f;
        v1 = ok ? w3[(size_t)r * DM + c + 1] : 0.0f;
        dst = w316 + j;
    } else {
        int j = i - CV3;
        int r = j / DFFP, c = j - r * DFFP;         // c even; row never straddled
        v0 = (c     < DFF) ? w2[(size_t)r * DFF + c]     : 0.0f;
        v1 = (c + 1 < DFF) ? w2[(size_t)r * DFF + c + 1] : 0.0f;
        dst = w216 + j;
    }
    *reinterpret_cast<__half2*>(dst) =
        __half2(__float2half_rn(v0), __float2half_rn(v1));
}

// ------------------------------- rmsnorm (step 5) ---------------------------
__global__ void __launch_bounds__(256)
rmsnorm_f16_kernel(const float* __restrict__ x, const float* __restrict__ w,
                   f16* __restrict__ oh)
{
    rmsnorm_row(x, w, oh, blockIdx.x, threadIdx.x);
}

// --------------------- fused scan (local + barrier + fixup) -----------------
DEV_INLINE float lam_of(const float* ll, int n) {
    return 1.0f / (1.0f + expf(-ll[n]));
}

__global__ void __launch_bounds__(NS)
scan_fused_kernel(const float* __restrict__ Bu, float* __restrict__ Hc,
                  const float* __restrict__ ll, f16* __restrict__ oh)
{
    extern __shared__ float sh[];                 // [CLEN][NS]
    const int bc = blockIdx.x, b = bc / NCHUNK, c = bc % NCHUNK;
    const int n = threadIdx.x;
    const float lam = lam_of(ll, n);
    const size_t base = ((size_t)b * T_LEN + (size_t)c * CLEN) * NS + n;

    // phase 1: local scan into smem, chunk carry to global
    float h = 0.0f;
    #pragma unroll 4
    for (int i = 0; i < CLEN; ++i) {
        h = fmaf(lam, h, Bu[base + (size_t)i * NS]);
        sh[i * NS + n] = h;
    }
    Hc[bc * NS + n] = h;

    // software grid barrier (ticket-based; monotone counter, replay-safe)
    __shared__ int s_target;
    __syncthreads();                // all Hc stores issued program-order above
    if (n == 0) {
        __threadfence();            // release our Hc writes GPU-wide
        int ticket = atomicAdd(&g_scan_ctr, 1);
        s_target = (ticket / SCAN_GRID + 1) * SCAN_GRID;
    }
    __syncthreads();
    {
        const int target = s_target;
        volatile int* vc = &g_scan_ctr;
        while (*vc < target) { }
        __threadfence();            // acquire: other CTAs' Hc now visible
    }

    // phase 2: carry prefix (identical fmaf chain to old scan_carry) + fixup
    float lamP = lam;
    #pragma unroll
    for (int j = 0; j < 6; ++j) lamP *= lamP;     // lam^64 == lam^CLEN
    float h0 = 0.0f;
    for (int j = 0; j < c; ++j)
        h0 = fmaf(lamP, h0, Hc[(b * NCHUNK + j) * NS + n]);
    float p = lam;
    #pragma unroll 4
    for (int i = 0; i < CLEN; ++i) {
        float v = fmaf(p, h0, sh[i * NS + n]);    // h0==0 for c==0
        oh[base + (size_t)i * NS] = __float2half_rn(v);
        p *= lam;
    }
}
constexpr int SMEM_SCAN = CLEN * NS * 4;          // 65536

// ----------------------- fp16 tensor-core GEMM (3-stage) -------------------
// C[M,N] = A@B^T, fp32 accum. BM=BN=128, BK=32, 8 warps (2x4), warp 64x32.
// NOTE: no minBlocks clause — R12 showed any reg cap below ~102 spills.
constexpr int RSB   = 80;               // smem row stride bytes (32 f16 + pad)
constexpr int TILE1 = 128 * RSB;        // 10240
constexpr int STG   = 2 * TILE1;        // A + B = 20480
constexpr int SMEM_GEMM = 3 * STG;      // 61440

enum { EPI_NONE = 0, EPI_SSM = 1, EPI_ADD = 2 };

template <int EPI>
__global__ void __launch_bounds__(256)
gemm_kernel(const f16* __restrict__ Ah, const f16* __restrict__ Bw,
            float* __restrict__ C, int M, int N, int K,
            const float* __restrict__ res, const f16* __restrict__ uaux,
            const float* __restrict__ dskip)
{
    extern __shared__ char smem[];
    const uint32_t sb = s2u(smem);
    const int tid = threadIdx.x, lane = tid & 31, wid = tid >> 5;
    const int mBase = blockIdx.y * 128, nBase = blockIdx.x * 128;
    const int wm = wid >> 2, wn = wid & 3;

    const int lr = tid >> 1;
    const int lc = (tid & 1) * 2;
    const size_t aoff = (size_t)(mBase + lr) * K;
    const size_t boff = (size_t)(nBase + lr) * K;

    const int lrow = (lane & 7) | (((lane >> 3) & 1) << 3);
    const int lkb  = lane >> 4;

    float acc[4][4][4];
    #pragma unroll
    for (int i = 0; i < 4; ++i)
        #pragma unroll
        for (int j = 0; j < 4; ++j)
            #pragma unroll
            for (int q = 0; q < 4; ++q) acc[i][j][q] = 0.0f;

    const int KT = K / 32;

    auto LOAD = [&](int kt, int s) {
        uint32_t base = sb + s * STG;
        #pragma unroll
        for (int j = 0; j < 2; ++j) {
            int c = lc + j;
            uint32_t dst = base + lr * RSB + c * 16;
            cpa16(dst,         Ah + aoff + kt * 32 + c * 8);
            cpa16(dst + TILE1, Bw + boff + kt * 32 + c * 8);
        }
        cp_commit();
    };

    LOAD(0, 0);
    if (KT > 1) LOAD(1, 1);

    int s = 0;
    for (int kt = 0; kt < KT; ++kt) {
        cp_wait<1>();
        __syncthreads();
        if (kt + 2 < KT) LOAD(kt + 2, (s + 2 >= 3) ? s - 1 : s + 2);

        const uint32_t base = sb + s * STG;
        #pragma unroll
        for (int ss = 0; ss < 2; ++ss) {
            const uint32_t kofs = ss * 32;
            uint32_t af[4][4], bf[4][2];
            #pragma unroll
            for (int mt = 0; mt < 4; ++mt) {
                uint32_t ad = base + (uint32_t)(wm*64 + mt*16 + lrow) * RSB
                            + kofs + lkb * 16;
                ldm4(af[mt], ad);
            }
            #pragma unroll
            for (int p = 0; p < 2; ++p) {
                uint32_t bd = base + TILE1
                            + (uint32_t)(wn*32 + p*16 + lrow) * RSB
                            + kofs + lkb * 16;
                uint32_t r[4];
                ldm4(r, bd);
                bf[2*p][0]   = r[0]; bf[2*p][1]   = r[2];
                bf[2*p+1][0] = r[1]; bf[2*p+1][1] = r[3];
            }
            #pragma unroll
            for (int mt = 0; mt < 4; ++mt)
                #pragma unroll
                for (int nt = 0; nt < 4; ++nt)
                    mma16816(acc[mt][nt], af[mt], bf[nt]);
        }
        s = (s + 1 >= 3) ? 0 : s + 1;
    }
    __syncthreads();

    // epilogue
    const int g = lane >> 2, t = lane & 3;
    #pragma unroll
    for (int mt = 0; mt < 4; ++mt) {
        #pragma unroll
        for (int nt = 0; nt < 4; ++nt) {
            const int col  = nBase + wn*32 + nt*8 + t*2;
            const int row0 = mBase + wm*64 + mt*16 + g;
            const int row1 = row0 + 8;
            float2 v0 = make_float2(acc[mt][nt][0], acc[mt][nt][1]);
            float2 v1 = make_float2(acc[mt][nt][2], acc[mt][nt][3]);
            const size_t o0 = (size_t)row0 * N + col;
            const size_t o1 = (size_t)row1 * N + col;
            if (EPI == EPI_SSM) {
                float2 d  = *reinterpret_cast<const float2*>(dskip + col);
                float2 r0 = *reinterpret_cast<const float2*>(res + o0);
                float2 r1 = *reinterpret_cast<const float2*>(res + o1);
                v0.x += r0.x; v0.y += r0.y;
                v1.x += r1.x; v1.y += r1.y;
                if (d.x != 0.0f || d.y != 0.0f) {   // skip u stream when D_skip==0
                    float2 u0 = __half22float2(
                        *reinterpret_cast<const __half2*>(uaux + o0));
                    float2 u1 = __half22float2(
                        *reinterpret_cast<const __half2*>(uaux + o1));
                    v0.x += d.x * u0.x; v0.y += d.y * u0.y;
                    v1.x += d.x * u1.x; v1.y += d.y * u1.y;
                }
            } else if (EPI == EPI_ADD) {
                float2 r0 = *reinterpret_cast<const float2*>(res + o0);
                float2 r1 = *reinterpret_cast<const float2*>(res + o1);
                v0.x += r0.x; v0.y += r0.y;
                v1.x += r1.x; v1.y += r1.y;
            }
            *reinterpret_cast<float2*>(C + o0) = v0;
            *reinterpret_cast<float2*>(C + o1) = v1;
        }
    }
}

// ------------------- dual SwiGLU fp16 GEMM (BN=64, 3-stage) -----------------
constexpr int TILB1 = 64 * RSB;                 // 5120
constexpr int STG_D = TILE1 + 2 * TILB1;        // 20480
constexpr int SMEM_DUAL = 3 * STG_D;            // 61440

__global__ void __launch_bounds__(256)
swiglu_kernel(const f16* __restrict__ Ah,
              const f16* __restrict__ W1, const f16* __restrict__ W3,
              f16* __restrict__ Gh, int M, int Kp, int K)
{
    extern __shared__ char smem[];
    const uint32_t sb = s2u(smem);
    const int tid = threadIdx.x, lane = tid & 31, wid = tid >> 5;
    const int mBase = blockIdx.y * 128, nBase = blockIdx.x * 64;
    const int wm = wid >> 2, wn = wid & 3;

    const int lra = tid >> 1, lca = (tid & 1) * 2;    // A loader
    const int lrb = tid >> 2, lcb = tid & 3;          // B loader
    const size_t aoff = (size_t)(mBase + lra) * K;
    const size_t boff = (size_t)(nBase + lrb) * K;    // weights padded

    const int lrow = (lane & 7) | (((lane >> 3) & 1) << 3);
    const int lkb  = lane >> 4;

    float accG[4][2][4], accV[4][2][4];
    #pragma unroll
    for (int i = 0; i < 4; ++i)
        #pragma unroll
        for (int j = 0; j < 2; ++j)
            #pragma unroll
            for (int q = 0; q < 4; ++q) { accG[i][j][q] = 0.0f; accV[i][j][q] = 0.0f; }

    const int KT = K / 32;

    auto LOAD = [&](int kt, int s) {
        uint32_t base = sb + s * STG_D;
        #pragma unroll
        for (int j = 0; j < 2; ++j) {
            int c = lca + j;
            cpa16(base + lra * RSB + c * 16, Ah + aoff + kt * 32 + c * 8);
        }
        {
            uint32_t dst = base + TILE1 + lrb * RSB + lcb * 16;
            const size_t go = boff + kt * 32 + lcb * 8;
            cpa16(dst,         W1 + go);
            cpa16(dst + TILB1, W3 + go);
        }
        cp_commit();
    };

    LOAD(0, 0);
    if (KT > 1) LOAD(1, 1);

    int s = 0;
    for (int kt = 0; kt < KT; ++kt) {
        cp_wait<1>();
        __syncthreads();
        if (kt + 2 < KT) LOAD(kt + 2, (s + 2 >= 3) ? s - 1 : s + 2);

        const uint32_t base = sb + s * STG_D;
        #pragma unroll
        for (int ss = 0; ss < 2; ++ss) {
            const uint32_t kofs = ss * 32;
            uint32_t af[4][4];
            uint32_t b1[2][2], b3[2][2];
            #pragma unroll
            for (int mt = 0; mt < 4; ++mt) {
                uint32_t ad = base + (uint32_t)(wm*64 + mt*16 + lrow) * RSB
                            + kofs + lkb * 16;
                ldm4(af[mt], ad);
            }
            {
                uint32_t bd = base + TILE1
                            + (uint32_t)(wn*16 + lrow) * RSB + kofs + lkb * 16;
                uint32_t r[4];
                ldm4(r, bd);
                b1[0][0]=r[0]; b1[0][1]=r[2]; b1[1][0]=r[1]; b1[1][1]=r[3];
                ldm4(r, bd + TILB1);
                b3[0][0]=r[0]; b3[0][1]=r[2]; b3[1][0]=r[1]; b3[1][1]=r[3];
            }
            #pragma unroll
            for (int mt = 0; mt < 4; ++mt)
                #pragma unroll
                for (int nt = 0; nt < 2; ++nt) {
                    mma16816(accG[mt][nt], af[mt], b1[nt]);
                    mma16816(accV[mt][nt], af[mt], b3[nt]);
                }
        }
        s = (s + 1 >= 3) ? 0 : s + 1;
    }
    __syncthreads();

    // epilogue: o = silu(gate) * val, fp16 round, strided Kp
    const int g = lane >> 2, t = lane & 3;
    #pragma unroll
    for (int mt = 0; mt < 4; ++mt) {
        #pragma unroll
        for (int nt = 0; nt < 2; ++nt) {
            const int col  = nBase + wn*16 + nt*8 + t*2;
            const int row0 = mBase + wm*64 + mt*16 + g;
            #pragma unroll
            for (int half = 0; half < 2; ++half) {
                const int row = row0 + half * 8;
                float gg0 = accG[mt][nt][half*2],   gg1 = accG[mt][nt][half*2+1];
                float vv0 = accV[mt][nt][half*2],   vv1 = accV[mt][nt][half*2+1];
                float o0 = gg0 / (1.0f + __expf(-gg0)) * vv0;
                float o1 = gg1 / (1.0f + __expf(-gg1)) * vv1;
                const size_t off = (size_t)row * Kp + col;
                *reinterpret_cast<__half2*>(Gh + off) =
                    __half2(__float2half_rn(o0), __float2half_rn(o1));
            }
        }
    }
}

// ------------------------------- launch -------------------------------------
extern "C" void kernel_launch(void* const* d_in, const int* in_sizes, int n_in,
                              void* d_out, int out_size)
{
    (void)in_sizes; (void)n_in; (void)out_size;
    const float* x        = (const float*)d_in[0];
    const float* log_lam  = (const float*)d_in[1];
    const float* B_w      = (const float*)d_in[2];
    const float* C_w      = (const float*)d_in[3];
    const float* D_skip   = (const float*)d_in[4];
    const float* ssm_w    = (const float*)d_in[5];
    const float* ffn_w    = (const float*)d_in[6];
    const float* w1       = (const float*)d_in[7];
    const float* w2       = (const float*)d_in[8];
    const float* w3       = (const float*)d_in[9];
    float* out = (float*)d_out;

    cudaFuncSetAttribute((const void*)gemm_kernel<EPI_NONE>,
        cudaFuncAttributeMaxDynamicSharedMemorySize, SMEM_GEMM);
    cudaFuncSetAttribute((const void*)gemm_kernel<EPI_SSM>,
        cudaFuncAttributeMaxDynamicSharedMemorySize, SMEM_GEMM);
    cudaFuncSetAttribute((const void*)gemm_kernel<EPI_ADD>,
        cudaFuncAttributeMaxDynamicSharedMemorySize, SMEM_GEMM);
    cudaFuncSetAttribute((const void*)swiglu_kernel,
        cudaFuncAttributeMaxDynamicSharedMemorySize, SMEM_DUAL);
    cudaFuncSetAttribute((const void*)scan_fused_kernel,
        cudaFuncAttributeMaxDynamicSharedMemorySize, SMEM_SCAN);

    float *Bu, *x1, *Hc;
    f16 *uh, *hsh, *zh, *gh;
    f16 *Bw16, *Cw16, *w116, *w316, *w216;
    cudaGetSymbolAddress((void**)&Bu,   g_Bu);
    cudaGetSymbolAddress((void**)&x1,   g_x1);
    cudaGetSymbolAddress((void**)&Hc,   g_Hc);
    cudaGetSymbolAddress((void**)&uh,   g_uh);
    cudaGetSymbolAddress((void**)&hsh,  g_hsh);
    cudaGetSymbolAddress((void**)&zh,   g_zh);
    cudaGetSymbolAddress((void**)&gh,   g_gh);
    cudaGetSymbolAddress((void**)&Bw16, g_Bw16);
    cudaGetSymbolAddress((void**)&Cw16, g_Cw16);
    cudaGetSymbolAddress((void**)&w116, g_w116);
    cudaGetSymbolAddress((void**)&w316, g_w316);
    cudaGetSymbolAddress((void**)&w216, g_w216);

    // 0+1) uh = fp16(rmsnorm(x, ssm_norm_w)) AND all weight conversions
    rms1_conv_kernel<<<MROWS + CONVB, 256>>>(
        x, ssm_w, uh, B_w, C_w, w1, w3, w2,
        Bw16, Cw16, w116, w316, w216);

    // 2) Bu = u @ B_w^T  [16384, 256], K=1024
    gemm_kernel<EPI_NONE><<<dim3(NS/128, MROWS/128), 256, SMEM_GEMM>>>(
        uh, Bw16, Bu, MROWS, NS, DM, nullptr, nullptr, nullptr);

    // 3) fused chunked diagonal scan -> hsh (fp16), single launch
    scan_fused_kernel<<<SCAN_GRID, NS, SMEM_SCAN>>>(Bu, Hc, log_lam, hsh);

    // 4) x1 = x + hs @ C_w^T + D_skip * u  [16384, 1024], K=256
    gemm_kernel<EPI_SSM><<<dim3(DM/128, MROWS/128), 256, SMEM_GEMM>>>(
        hsh, Cw16, x1, MROWS, DM, NS, x, uh, D_skip);

    // 5) zh = fp16(rmsnorm(x1, ffn_norm_w))
    rmsnorm_f16_kernel<<<MROWS, 256>>>(x1, ffn_w, zh);

    // 6) gh = fp16(silu(z@w1^T) * (z@w3^T))  [16384, 2752-padded], K=1024
    swiglu_kernel<<<dim3(DFFP/64, MROWS/128), 256, SMEM_DUAL>>>(
        zh, w116, w316, gh, MROWS, DFFP, DM);

    // 7) out = x1 + g @ w2^T  [16384, 1024], K=2752
    gemm_kernel<EPI_ADD><<<dim3(DM/128, MROWS/128), 256, SMEM_GEMM>>>(
        gh, w216, out, MROWS, DM, DFFP, x1, nullptr, nullptr);
}

// round 16
// speedup vs baseline: 1.2182x; 1.0404x over previous
#include <cuda_runtime.h>
#include <cuda_fp16.h>
#include <cstdint>

#define DEV_INLINE __device__ __forceinline__

using f16 = __half;

constexpr int B_SZ  = 4;
constexpr int T_LEN = 4096;
constexpr int DM    = 1024;
constexpr int NS    = 256;
constexpr int DFF   = 2736;
constexpr int DFFP  = 2752;            // padded to /64
constexpr int MROWS = B_SZ * T_LEN;    // 16384
constexpr float EPSN = 1e-6f;

constexpr int CLEN   = 64;
constexpr int NCHUNK = T_LEN / CLEN;   // 64
constexpr int SCAN_GRID = B_SZ * NCHUNK;  // 256

// ------------------------------- scratch -----------------------------------
__device__ float g_Bu[(size_t)MROWS * NS];
__device__ float g_x1[(size_t)MROWS * DM];
__device__ float g_Hc[SCAN_GRID * NS];
__device__ int   g_scan_ctr;            // monotone ticket counter (never reset)

__device__ f16 g_uh [(size_t)MROWS * DM];
__device__ f16 g_hsh[(size_t)MROWS * NS];
__device__ f16 g_zh [(size_t)MROWS * DM];
__device__ f16 g_gh [(size_t)MROWS * DFFP];

// fp16 weights (single copy; padded tails zero)
__device__ f16 g_Bw16[NS * DM];
__device__ f16 g_Cw16[DM * NS];
__device__ f16 g_w116[DFFP * DM];
__device__ f16 g_w316[DFFP * DM];
__device__ f16 g_w216[DM * DFFP];

// ------------------------------- PTX helpers -------------------------------
DEV_INLINE uint32_t s2u(const void* p) {
    return (uint32_t)__cvta_generic_to_shared(p);
}
DEV_INLINE void cpa16(uint32_t dst, const void* src) {
    asm volatile("cp.async.cg.shared.global [%0], [%1], 16;\n"
                 :: "r"(dst), "l"(src));
}
DEV_INLINE void cp_commit() { asm volatile("cp.async.commit_group;\n"); }
template <int N> DEV_INLINE void cp_wait() {
    asm volatile("cp.async.wait_group %0;\n" :: "n"(N));
}
DEV_INLINE void ldm4(uint32_t* r, uint32_t a) {
    asm volatile("ldmatrix.sync.aligned.m8n8.x4.shared.b16 {%0,%1,%2,%3}, [%4];\n"
                 : "=r"(r[0]), "=r"(r[1]), "=r"(r[2]), "=r"(r[3]) : "r"(a));
}
DEV_INLINE void mma16816(float* c, const uint32_t* a, const uint32_t* b) {
    asm volatile(
        "mma.sync.aligned.m16n8k16.row.col.f32.f16.f16.f32 "
        "{%0,%1,%2,%3}, {%4,%5,%6,%7}, {%8,%9}, {%0,%1,%2,%3};\n"
        : "+f"(c[0]), "+f"(c[1]), "+f"(c[2]), "+f"(c[3])
        : "r"(a[0]), "r"(a[1]), "r"(a[2]), "r"(a[3]), "r"(b[0]), "r"(b[1]));
}

// -------------------- fused rmsnorm1 + weight conversion --------------------
constexpr int CV0 = NS * DM;                 // Bw
constexpr int CV1 = CV0 + DM * NS;           // Cw
constexpr int CV2 = CV1 + DFFP * DM;         // w1 (padrow)
constexpr int CV3 = CV2 + DFFP * DM;         // w3 (padrow)
constexpr int CV4 = CV3 + DM * DFFP;         // w2 (padcol)
constexpr int CONVB = (CV4 / 2 + 255) / 256;

DEV_INLINE void rmsnorm_row(const float* __restrict__ x,
                            const float* __restrict__ w,
                            f16* __restrict__ oh, int row, int tid)
{
    float4 v = reinterpret_cast<const float4*>(x + (size_t)row * DM)[tid];
    float ss = v.x*v.x + v.y*v.y + v.z*v.z + v.w*v.w;
    #pragma unroll
    for (int o = 16; o; o >>= 1) ss += __shfl_xor_sync(0xffffffffu, ss, o);
    __shared__ float red[8];
    if ((tid & 31) == 0) red[tid >> 5] = ss;
    __syncthreads();
    float tot = red[0]+red[1]+red[2]+red[3]+red[4]+red[5]+red[6]+red[7];
    float inv = rsqrtf(tot * (1.0f / (float)DM) + EPSN);
    float4 wv = reinterpret_cast<const float4*>(w)[tid];
    __half2* ph = reinterpret_cast<__half2*>(oh + (size_t)row * DM);
    ph[tid*2]   = __half2(__float2half_rn(v.x*inv*wv.x), __float2half_rn(v.y*inv*wv.y));
    ph[tid*2+1] = __half2(__float2half_rn(v.z*inv*wv.z), __float2half_rn(v.w*inv*wv.w));
}

__global__ void __launch_bounds__(256)
rms1_conv_kernel(const float* __restrict__ x, const float* __restrict__ ssw,
                 f16* __restrict__ uh,
                 const float* __restrict__ B_w, const float* __restrict__ C_w,
                 const float* __restrict__ w1,  const float* __restrict__ w3,
                 const float* __restrict__ w2,
                 f16* __restrict__ Bw16, f16* __restrict__ Cw16,
                 f16* __restrict__ w116, f16* __restrict__ w316,
                 f16* __restrict__ w216)
{
    if (blockIdx.x < MROWS) {
        rmsnorm_row(x, ssw, uh, blockIdx.x, threadIdx.x);
        return;
    }
    const int i = 2 * ((blockIdx.x - MROWS) * blockDim.x + threadIdx.x);
    if (i >= CV4) return;
    float v0, v1;
    f16* dst;
    if (i < CV0) {
        v0 = B_w[i]; v1 = B_w[i + 1]; dst = Bw16 + i;
    } else if (i < CV1) {
        int j = i - CV0;
        v0 = C_w[j]; v1 = C_w[j + 1]; dst = Cw16 + j;
    } else if (i < CV2) {
        int j = i - CV1;
        int r = j >> 10, c = j & 1023;              // DM = 1024
        bool ok = r < DFF;
        v0 = ok ? w1[(size_t)r * DM + c]     : 0.0f;
        v1 = ok ? w1[(size_t)r * DM + c + 1] : 0.0f;
        dst = w116 + j;
    } else if (i < CV3) {
        int j = i - CV2;
        int r = j >> 10, c = j & 1023;
        bool ok = r < DFF;
        v0 = ok ? w3[(size_t)r * DM + c]     : 0.0f;
        v1 = ok ? w3[(size_t)r * DM + c + 1] : 0.0f;
        dst = w316 + j;
    } else {
        int j = i - CV3;
        int r = j / DFFP, c = j - r * DFFP;         // c even; row never straddled
        v0 = (c     < DFF) ? w2[(size_t)r * DFF + c]     : 0.0f;
        v1 = (c + 1 < DFF) ? w2[(size_t)r * DFF + c + 1] : 0.0f;
        dst = w216 + j;
    }
    *reinterpret_cast<__half2*>(dst) =
        __half2(__float2half_rn(v0), __float2half_rn(v1));
}

// ------------------------------- rmsnorm (step 5) ---------------------------
__global__ void __launch_bounds__(256)
rmsnorm_f16_kernel(const float* __restrict__ x, const float* __restrict__ w,
                   f16* __restrict__ oh)
{
    rmsnorm_row(x, w, oh, blockIdx.x, threadIdx.x);
}

// --------------------- fused scan (local + barrier + fixup) -----------------
DEV_INLINE float lam_of(const float* ll, int n) {
    return 1.0f / (1.0f + expf(-ll[n]));
}

__global__ void __launch_bounds__(NS)
scan_fused_kernel(const float* __restrict__ Bu, float* __restrict__ Hc,
                  const float* __restrict__ ll, f16* __restrict__ oh)
{
    extern __shared__ float sh[];                 // [CLEN][NS]
    const int bc = blockIdx.x, b = bc / NCHUNK, c = bc % NCHUNK;
    const int n = threadIdx.x;
    const float lam = lam_of(ll, n);
    const size_t base = ((size_t)b * T_LEN + (size_t)c * CLEN) * NS + n;

    // phase 1: local scan into smem, chunk carry to global
    float h = 0.0f;
    #pragma unroll 4
    for (int i = 0; i < CLEN; ++i) {
        h = fmaf(lam, h, Bu[base + (size_t)i * NS]);
        sh[i * NS + n] = h;
    }
    Hc[bc * NS + n] = h;

    // software grid barrier (ticket-based; monotone counter, replay-safe)
    __shared__ int s_target;
    __syncthreads();                // all Hc stores issued program-order above
    if (n == 0) {
        __threadfence();            // release our Hc writes GPU-wide
        int ticket = atomicAdd(&g_scan_ctr, 1);
        s_target = (ticket / SCAN_GRID + 1) * SCAN_GRID;
    }
    __syncthreads();
    {
        const int target = s_target;
        volatile int* vc = &g_scan_ctr;
        while (*vc < target) { }
        __threadfence();            // acquire: other CTAs' Hc now visible
    }

    // phase 2: carry prefix (identical fmaf chain) + fixup
    float lamP = lam;
    #pragma unroll
    for (int j = 0; j < 6; ++j) lamP *= lamP;     // lam^64 == lam^CLEN
    float h0 = 0.0f;
    for (int j = 0; j < c; ++j)
        h0 = fmaf(lamP, h0, Hc[(b * NCHUNK + j) * NS + n]);
    float p = lam;
    #pragma unroll 4
    for (int i = 0; i < CLEN; ++i) {
        float v = fmaf(p, h0, sh[i * NS + n]);    // h0==0 for c==0
        oh[base + (size_t)i * NS] = __float2half_rn(v);
        p *= lam;
    }
}
constexpr int SMEM_SCAN = CLEN * NS * 4;          // 65536

// ----------------------- fp16 tensor-core GEMM (3-stage) -------------------
// C[M,N] = A@B^T, fp32 accum. BM=BN=128, BK=32, 8 warps (2x4), warp 64x32.
// All 12 ldm4 for BOTH k16 sub-steps are issued back-to-back (MLP over LDSM)
// before the 128 mma. __launch_bounds__(256,2) caps regs at 128 (2 CTAs/SM).
constexpr int RSB   = 80;               // smem row stride bytes (32 f16 + pad)
constexpr int TILE1 = 128 * RSB;        // 10240
constexpr int STG   = 2 * TILE1;        // A + B = 20480
constexpr int SMEM_GEMM = 3 * STG;      // 61440

enum { EPI_NONE = 0, EPI_SSM = 1, EPI_ADD = 2 };

template <int EPI>
__global__ void __launch_bounds__(256, 2)
gemm_kernel(const f16* __restrict__ Ah, const f16* __restrict__ Bw,
            float* __restrict__ C, int M, int N, int K,
            const float* __restrict__ res, const f16* __restrict__ uaux,
            const float* __restrict__ dskip)
{
    extern __shared__ char smem[];
    const uint32_t sb = s2u(smem);
    const int tid = threadIdx.x, lane = tid & 31, wid = tid >> 5;
    const int mBase = blockIdx.y * 128, nBase = blockIdx.x * 128;
    const int wm = wid >> 2, wn = wid & 3;

    const int lr = tid >> 1;
    const int lc = (tid & 1) * 2;
    const size_t aoff = (size_t)(mBase + lr) * K;
    const size_t boff = (size_t)(nBase + lr) * K;

    const int lrow = (lane & 7) | (((lane >> 3) & 1) << 3);
    const int lkb  = lane >> 4;

    float acc[4][4][4];
    #pragma unroll
    for (int i = 0; i < 4; ++i)
        #pragma unroll
        for (int j = 0; j < 4; ++j)
            #pragma unroll
            for (int q = 0; q < 4; ++q) acc[i][j][q] = 0.0f;

    const int KT = K / 32;

    auto LOAD = [&](int kt, int s) {
        uint32_t base = sb + s * STG;
        #pragma unroll
        for (int j = 0; j < 2; ++j) {
            int c = lc + j;
            uint32_t dst = base + lr * RSB + c * 16;
            cpa16(dst,         Ah + aoff + kt * 32 + c * 8);
            cpa16(dst + TILE1, Bw + boff + kt * 32 + c * 8);
        }
        cp_commit();
    };

    LOAD(0, 0);
    if (KT > 1) LOAD(1, 1);

    int s = 0;
    for (int kt = 0; kt < KT; ++kt) {
        cp_wait<1>();
        __syncthreads();
        if (kt + 2 < KT) LOAD(kt + 2, (s + 2 >= 3) ? s - 1 : s + 2);

        const uint32_t base = sb + s * STG;
        uint32_t af[2][4][4], bf[2][4][2];
        // issue ALL fragment loads for both sub-steps back-to-back
        #pragma unroll
        for (int ss = 0; ss < 2; ++ss) {
            const uint32_t kofs = ss * 32;
            #pragma unroll
            for (int mt = 0; mt < 4; ++mt) {
                uint32_t ad = base + (uint32_t)(wm*64 + mt*16 + lrow) * RSB
                            + kofs + lkb * 16;
                ldm4(af[ss][mt], ad);
            }
            #pragma unroll
            for (int p = 0; p < 2; ++p) {
                uint32_t bd = base + TILE1
                            + (uint32_t)(wn*32 + p*16 + lrow) * RSB
                            + kofs + lkb * 16;
                uint32_t r[4];
                ldm4(r, bd);
                bf[ss][2*p][0]   = r[0]; bf[ss][2*p][1]   = r[2];
                bf[ss][2*p+1][0] = r[1]; bf[ss][2*p+1][1] = r[3];
            }
        }
        #pragma unroll
        for (int ss = 0; ss < 2; ++ss)
            #pragma unroll
            for (int mt = 0; mt < 4; ++mt)
                #pragma unroll
                for (int nt = 0; nt < 4; ++nt)
                    mma16816(acc[mt][nt], af[ss][mt], bf[ss][nt]);
        s = (s + 1 >= 3) ? 0 : s + 1;
    }
    __syncthreads();

    // epilogue
    const int g = lane >> 2, t = lane & 3;
    #pragma unroll
    for (int mt = 0; mt < 4; ++mt) {
        #pragma unroll
        for (int nt = 0; nt < 4; ++nt) {
            const int col  = nBase + wn*32 + nt*8 + t*2;
            const int row0 = mBase + wm*64 + mt*16 + g;
            const int row1 = row0 + 8;
            float2 v0 = make_float2(acc[mt][nt][0], acc[mt][nt][1]);
            float2 v1 = make_float2(acc[mt][nt][2], acc[mt][nt][3]);
            const size_t o0 = (size_t)row0 * N + col;
            const size_t o1 = (size_t)row1 * N + col;
            if (EPI == EPI_SSM) {
                float2 d  = *reinterpret_cast<const float2*>(dskip + col);
                float2 r0 = *reinterpret_cast<const float2*>(res + o0);
                float2 r1 = *reinterpret_cast<const float2*>(res + o1);
                v0.x += r0.x; v0.y += r0.y;
                v1.x += r1.x; v1.y += r1.y;
                if (d.x != 0.0f || d.y != 0.0f) {   // skip u stream when D_skip==0
                    float2 u0 = __half22float2(
                        *reinterpret_cast<const __half2*>(uaux + o0));
                    float2 u1 = __half22float2(
                        *reinterpret_cast<const __half2*>(uaux + o1));
                    v0.x += d.x * u0.x; v0.y += d.y * u0.y;
                    v1.x += d.x * u1.x; v1.y += d.y * u1.y;
                }
            } else if (EPI == EPI_ADD) {
                float2 r0 = *reinterpret_cast<const float2*>(res + o0);
                float2 r1 = *reinterpret_cast<const float2*>(res + o1);
                v0.x += r0.x; v0.y += r0.y;
                v1.x += r1.x; v1.y += r1.y;
            }
            *reinterpret_cast<float2*>(C + o0) = v0;
            *reinterpret_cast<float2*>(C + o1) = v1;
        }
    }
}

// ------------------- dual SwiGLU fp16 GEMM (BN=64, 3-stage) -----------------
// A fragments for both sub-steps loaded up front (B fragments stay per-step:
// full doubling would exceed the 128-reg 2-CTA budget).
constexpr int TILB1 = 64 * RSB;                 // 5120
constexpr int STG_D = TILE1 + 2 * TILB1;        // 20480
constexpr int SMEM_DUAL = 3 * STG_D;            // 61440

__global__ void __launch_bounds__(256, 2)
swiglu_kernel(const f16* __restrict__ Ah,
              const f16* __restrict__ W1, const f16* __restrict__ W3,
              f16* __restrict__ Gh, int M, int Kp, int K)
{
    extern __shared__ char smem[];
    const uint32_t sb = s2u(smem);
    const int tid = threadIdx.x, lane = tid & 31, wid = tid >> 5;
    const int mBase = blockIdx.y * 128, nBase = blockIdx.x * 64;
    const int wm = wid >> 2, wn = wid & 3;

    const int lra = tid >> 1, lca = (tid & 1) * 2;    // A loader
    const int lrb = tid >> 2, lcb = tid & 3;          // B loader
    const size_t aoff = (size_t)(mBase + lra) * K;
    const size_t boff = (size_t)(nBase + lrb) * K;    // weights padded

    const int lrow = (lane & 7) | (((lane >> 3) & 1) << 3);
    const int lkb  = lane >> 4;

    float accG[4][2][4], accV[4][2][4];
    #pragma unroll
    for (int i = 0; i < 4; ++i)
        #pragma unroll
        for (int j = 0; j < 2; ++j)
            #pragma unroll
            for (int q = 0; q < 4; ++q) { accG[i][j][q] = 0.0f; accV[i][j][q] = 0.0f; }

    const int KT = K / 32;

    auto LOAD = [&](int kt, int s) {
        uint32_t base = sb + s * STG_D;
        #pragma unroll
        for (int j = 0; j < 2; ++j) {
            int c = lca + j;
            cpa16(base + lra * RSB + c * 16, Ah + aoff + kt * 32 + c * 8);
        }
        {
            uint32_t dst = base + TILE1 + lrb * RSB + lcb * 16;
            const size_t go = boff + kt * 32 + lcb * 8;
            cpa16(dst,         W1 + go);
            cpa16(dst + TILB1, W3 + go);
        }
        cp_commit();
    };

    LOAD(0, 0);
    if (KT > 1) LOAD(1, 1);

    int s = 0;
    for (int kt = 0; kt < KT; ++kt) {
        cp_wait<1>();
        __syncthreads();
        if (kt + 2 < KT) LOAD(kt + 2, (s + 2 >= 3) ? s - 1 : s + 2);

        const uint32_t base = sb + s * STG_D;
        uint32_t af[2][4][4];
        // A fragments for both sub-steps up front
        #pragma unroll
        for (int ss = 0; ss < 2; ++ss) {
            const uint32_t kofs = ss * 32;
            #pragma unroll
            for (int mt = 0; mt < 4; ++mt) {
                uint32_t ad = base + (uint32_t)(wm*64 + mt*16 + lrow) * RSB
                            + kofs + lkb * 16;
                ldm4(af[ss][mt], ad);
            }
        }
        #pragma unroll
        for (int ss = 0; ss < 2; ++ss) {
            const uint32_t kofs = ss * 32;
            uint32_t b1[2][2], b3[2][2];
            {
                uint32_t bd = base + TILE1
                            + (uint32_t)(wn*16 + lrow) * RSB + kofs + lkb * 16;
                uint32_t r[4];
                ldm4(r, bd);
                b1[0][0]=r[0]; b1[0][1]=r[2]; b1[1][0]=r[1]; b1[1][1]=r[3];
                ldm4(r, bd + TILB1);
                b3[0][0]=r[0]; b3[0][1]=r[2]; b3[1][0]=r[1]; b3[1][1]=r[3];
            }
            #pragma unroll
            for (int mt = 0; mt < 4; ++mt)
                #pragma unroll
                for (int nt = 0; nt < 2; ++nt) {
                    mma16816(accG[mt][nt], af[ss][mt], b1[nt]);
                    mma16816(accV[mt][nt], af[ss][mt], b3[nt]);
                }
        }
        s = (s + 1 >= 3) ? 0 : s + 1;
    }
    __syncthreads();

    // epilogue: o = silu(gate) * val, fp16 round, strided Kp
    const int g = lane >> 2, t = lane & 3;
    #pragma unroll
    for (int mt = 0; mt < 4; ++mt) {
        #pragma unroll
        for (int nt = 0; nt < 2; ++nt) {
            const int col  = nBase + wn*16 + nt*8 + t*2;
            const int row0 = mBase + wm*64 + mt*16 + g;
            #pragma unroll
            for (int half = 0; half < 2; ++half) {
                const int row = row0 + half * 8;
                float gg0 = accG[mt][nt][half*2],   gg1 = accG[mt][nt][half*2+1];
                float vv0 = accV[mt][nt][half*2],   vv1 = accV[mt][nt][half*2+1];
                float o0 = gg0 / (1.0f + __expf(-gg0)) * vv0;
                float o1 = gg1 / (1.0f + __expf(-gg1)) * vv1;
                const size_t off = (size_t)row * Kp + col;
                *reinterpret_cast<__half2*>(Gh + off) =
                    __half2(__float2half_rn(o0), __float2half_rn(o1));
            }
        }
    }
}

// ------------------------------- launch -------------------------------------
extern "C" void kernel_launch(void* const* d_in, const int* in_sizes, int n_in,
                              void* d_out, int out_size)
{
    (void)in_sizes; (void)n_in; (void)out_size;
    const float* x        = (const float*)d_in[0];
    const float* log_lam  = (const float*)d_in[1];
    const float* B_w      = (const float*)d_in[2];
    const float* C_w      = (const float*)d_in[3];
    const float* D_skip   = (const float*)d_in[4];
    const float* ssm_w    = (const float*)d_in[5];
    const float* ffn_w    = (const float*)d_in[6];
    const float* w1       = (const float*)d_in[7];
    const float* w2       = (const float*)d_in[8];
    const float* w3       = (const float*)d_in[9];
    float* out = (float*)d_out;

    cudaFuncSetAttribute((const void*)gemm_kernel<EPI_NONE>,
        cudaFuncAttributeMaxDynamicSharedMemorySize, SMEM_GEMM);
    cudaFuncSetAttribute((const void*)gemm_kernel<EPI_SSM>,
        cudaFuncAttributeMaxDynamicSharedMemorySize, SMEM_GEMM);
    cudaFuncSetAttribute((const void*)gemm_kernel<EPI_ADD>,
        cudaFuncAttributeMaxDynamicSharedMemorySize, SMEM_GEMM);
    cudaFuncSetAttribute((const void*)swiglu_kernel,
        cudaFuncAttributeMaxDynamicSharedMemorySize, SMEM_DUAL);
    cudaFuncSetAttribute((const void*)scan_fused_kernel,
        cudaFuncAttributeMaxDynamicSharedMemorySize, SMEM_SCAN);

    float *Bu, *x1, *Hc;
    f16 *uh, *hsh, *zh, *gh;
    f16 *Bw16, *Cw16, *w116, *w316, *w216;
    cudaGetSymbolAddress((void**)&Bu,   g_Bu);
    cudaGetSymbolAddress((void**)&x1,   g_x1);
    cudaGetSymbolAddress((void**)&Hc,   g_Hc);
    cudaGetSymbolAddress((void**)&uh,   g_uh);
    cudaGetSymbolAddress((void**)&hsh,  g_hsh);
    cudaGetSymbolAddress((void**)&zh,   g_zh);
    cudaGetSymbolAddress((void**)&gh,   g_gh);
    cudaGetSymbolAddress((void**)&Bw16, g_Bw16);
    cudaGetSymbolAddress((void**)&Cw16, g_Cw16);
    cudaGetSymbolAddress((void**)&w116, g_w116);
    cudaGetSymbolAddress((void**)&w316, g_w316);
    cudaGetSymbolAddress((void**)&w216, g_w216);

    // 0+1) uh = fp16(rmsnorm(x, ssm_norm_w)) AND all weight conversions
    rms1_conv_kernel<<<MROWS + CONVB, 256>>>(
        x, ssm_w, uh, B_w, C_w, w1, w3, w2,
        Bw16, Cw16, w116, w316, w216);

    // 2) Bu = u @ B_w^T  [16384, 256], K=1024
    gemm_kernel<EPI_NONE><<<dim3(NS/128, MROWS/128), 256, SMEM_GEMM>>>(
        uh, Bw16, Bu, MROWS, NS, DM, nullptr, nullptr, nullptr);

    // 3) fused chunked diagonal scan -> hsh (fp16), single launch
    scan_fused_kernel<<<SCAN_GRID, NS, SMEM_SCAN>>>(Bu, Hc, log_lam, hsh);

    // 4) x1 = x + hs @ C_w^T + D_skip * u  [16384, 1024], K=256
    gemm_kernel<EPI_SSM><<<dim3(DM/128, MROWS/128), 256, SMEM_GEMM>>>(
        hsh, Cw16, x1, MROWS, DM, NS, x, uh, D_skip);

    // 5) zh = fp16(rmsnorm(x1, ffn_norm_w))
    rmsnorm_f16_kernel<<<MROWS, 256>>>(x1, ffn_w, zh);

    // 6) gh = fp16(silu(z@w1^T) * (z@w3^T))  [16384, 2752-padded], K=1024
    swiglu_kernel<<<dim3(DFFP/64, MROWS/128), 256, SMEM_DUAL>>>(
        zh, w116, w316, gh, MROWS, DFFP, DM);

    // 7) out = x1 + g @ w2^T  [16384, 1024], K=2752
    gemm_kernel<EPI_ADD><<<dim3(DM/128, MROWS/128), 256, SMEM_GEMM>>>(
        gh, w216, out, MROWS, DM, DFFP, x1, nullptr, nullptr);
}